// round 2
// baseline (speedup 1.0000x reference)
#include <cuda_runtime.h>
#include <cstdint>

#define N_PTS 8192
#define DIM 64
#define BM 128
#define BN 128
#define JSPLIT 16
#define JCHUNK (N_PTS / JSPLIT)   // 512
#define JTILES (JCHUNK / BN)      // 4
#define NTHREADS 256

// Scratch (no allocation allowed). ALL writes below are idempotent pure
// functions of the inputs — no atomics, no zero-then-accumulate — so the
// kernels are race-immune under any graph replay/overlap pattern.
__device__ float g_sq[N_PTS];
__device__ float g_ru[N_PTS];                 // 1/(1 - ||x||^2)
__device__ int   g_lab[N_PTS];
__device__ float g_pse[JSPLIT * N_PTS];       // partial sum exp(-d)
__device__ float g_psl[JSPLIT * N_PTS];       // partial sum of log r over positives
__device__ int   g_pct[JSPLIT * N_PTS];       // partial positive counts
__device__ float g_rowloss[N_PTS];

__global__ void prep_kernel(const float* __restrict__ pts,
                            const long long* __restrict__ labs) {
    int i = blockIdx.x * blockDim.x + threadIdx.x;
    if (i >= N_PTS) return;
    const float4* p = (const float4*)(pts + i * DIM);
    float s = 0.f;
#pragma unroll
    for (int q = 0; q < DIM / 4; q++) {
        float4 v = p[q];
        s += v.x * v.x + v.y * v.y + v.z * v.z + v.w * v.w;
    }
    g_sq[i] = s;
    g_ru[i] = 1.0f / (1.0f - s);   // norms < 0.9 strictly
    g_lab[i] = (int)labs[i];
}

__device__ __forceinline__ float fast_sqrt(float x) {
    float r; asm("sqrt.approx.f32 %0, %1;" : "=f"(r) : "f"(x)); return r;
}
__device__ __forceinline__ float fast_rcp(float x) {
    float r; asm("rcp.approx.f32 %0, %1;" : "=f"(r) : "f"(x)); return r;
}

__global__ __launch_bounds__(NTHREADS)
void main_kernel(const float* __restrict__ pts) {
    // As: [k][m] 64x128 (32KB, loaded once per block)
    // Bs: [kk][n] 32x128 (16KB, two k-halves per j-tile) -> 48KB static total
    __shared__ float As[DIM * BM];
    __shared__ float Bs[32 * BN];
    const float4* P4 = (const float4*)pts;
    int tid = threadIdx.x;
    int tx = tid & 15, ty = tid >> 4;
    int i0 = blockIdx.y * BM;
    int jbase = blockIdx.x * JCHUNK;

    // Load A tile transposed [k][m]
#pragma unroll
    for (int it = 0; it < (BM * DIM / 4) / NTHREADS; it++) {
        int idx = tid + it * NTHREADS;
        int m = idx & (BM - 1);
        int q = idx >> 7;                       // 0..15 (float4 index along k)
        float4 v = P4[(i0 + m) * (DIM / 4) + q];
        As[(4 * q + 0) * BM + m] = v.x;
        As[(4 * q + 1) * BM + m] = v.y;
        As[(4 * q + 2) * BM + m] = v.z;
        As[(4 * q + 3) * BM + m] = v.w;
    }

    float sumexp[8], prod[8];
    int eacc[8], cnt[8];
#pragma unroll
    for (int r = 0; r < 8; r++) { sumexp[r] = 0.f; prod[r] = 1.f; eacc[r] = 0; cnt[r] = 0; }

    for (int jt = 0; jt < JTILES; jt++) {
        int j0 = jbase + jt * BN;
        float acc[8][8];
#pragma unroll
        for (int r = 0; r < 8; r++)
#pragma unroll
            for (int c = 0; c < 8; c++) acc[r][c] = 0.f;

#pragma unroll
        for (int kh = 0; kh < 2; kh++) {
            __syncthreads();
#pragma unroll
            for (int it = 0; it < (BN * 32 / 4) / NTHREADS; it++) {
                int idx = tid + it * NTHREADS;
                int n = idx & (BN - 1);
                int q = idx >> 7;               // 0..7
                float4 v = P4[(j0 + n) * (DIM / 4) + kh * 8 + q];
                Bs[(4 * q + 0) * BN + n] = v.x;
                Bs[(4 * q + 1) * BN + n] = v.y;
                Bs[(4 * q + 2) * BN + n] = v.z;
                Bs[(4 * q + 3) * BN + n] = v.w;
            }
            __syncthreads();
#pragma unroll
            for (int kk = 0; kk < 32; kk++) {
                int k = kh * 32 + kk;
                float4 a0 = *(const float4*)&As[k * BM + ty * 4];
                float4 a1 = *(const float4*)&As[k * BM + 64 + ty * 4];
                float4 b0 = *(const float4*)&Bs[kk * BN + tx * 4];
                float4 b1 = *(const float4*)&Bs[kk * BN + 64 + tx * 4];
                float a[8] = {a0.x, a0.y, a0.z, a0.w, a1.x, a1.y, a1.z, a1.w};
                float b[8] = {b0.x, b0.y, b0.z, b0.w, b1.x, b1.y, b1.z, b1.w};
#pragma unroll
                for (int r = 0; r < 8; r++)
#pragma unroll
                    for (int c = 0; c < 8; c++)
                        acc[r][c] = fmaf(a[r], b[c], acc[r][c]);
            }
        }

        // Epilogue: r = exp(-arccosh(z)) = 1/(z + sqrt(z^2-1)); log r = -d.
        int gj[8], labj[8];
        float sqj[8], ruj[8];
#pragma unroll
        for (int c = 0; c < 8; c++) {
            int col = ((c & 4) << 4) + tx * 4 + (c & 3);
            int g = j0 + col;
            gj[c] = g; sqj[c] = g_sq[g]; ruj[c] = g_ru[g]; labj[c] = g_lab[g];
        }
#pragma unroll
        for (int r = 0; r < 8; r++) {
            int row = ((r & 4) << 4) + ty * 4 + (r & 3);
            int gi = i0 + row;
            float sqi  = g_sq[gi];
            float rui2 = 2.0f * g_ru[gi];
            int   labi = g_lab[gi];
            float se = 0.f;
            float pr = prod[r];
            int ct = 0;
#pragma unroll
            for (int c = 0; c < 8; c++) {
                float sqd = fmaxf(fmaf(-2.0f, acc[r][c], sqi + sqj[c]), 0.f);
                float z = fmaf(sqd * rui2, ruj[c], 1.0f);
                z = fmaxf(z, 1.0f + 1e-7f);
                float t = fmaf(z, z, -1.0f);
                float s = fast_sqrt(t);
                float rv = fast_rcp(z + s);      // exp(-d), no cancellation
                bool offd = (gi != gj[c]);
                if (offd) se += rv;
                if (offd && (labi == labj[c])) { pr *= rv; ct++; }
            }
            sumexp[r] += se;
            cnt[r] += ct;
            // renormalize mantissa product (pure ALU log accumulation)
            unsigned pb = __float_as_uint(pr);
            eacc[r] += (int)(pb >> 23) - 127;
            prod[r] = __uint_as_float((pb & 0x007FFFFFu) | 0x3F800000u);
        }
    }

    // 16-lane (same-ty) butterfly reduce, then plain idempotent stores into
    // disjoint (jsplit, row) slots — no atomics anywhere.
#pragma unroll
    for (int r = 0; r < 8; r++) {
        float se = sumexp[r];
        float sl = ((float)eacc[r] + __log2f(prod[r])) * 0.69314718055994531f;
        int ct = cnt[r];
#pragma unroll
        for (int s = 8; s > 0; s >>= 1) {
            se += __shfl_xor_sync(0xffffffffu, se, s);
            sl += __shfl_xor_sync(0xffffffffu, sl, s);
            ct += __shfl_xor_sync(0xffffffffu, ct, s);
        }
        if (tx == 0) {
            int row = ((r & 4) << 4) + ty * 4 + (r & 3);
            int gi = i0 + row;
            int slot = blockIdx.x * N_PTS + gi;
            g_pse[slot] = se;
            g_psl[slot] = sl;
            g_pct[slot] = ct;
        }
    }
}

// Fold the 16 j-split partials per row into a per-row loss (deterministic
// fixed-order reduction, pure function of g_p* arrays).
__global__ void rowred_kernel() {
    int i = blockIdx.x * blockDim.x + threadIdx.x;
    if (i >= N_PTS) return;
    float se = 0.f, sl = 0.f;
    int ct = 0;
#pragma unroll
    for (int js = 0; js < JSPLIT; js++) {
        se += g_pse[js * N_PTS + i];
        sl += g_psl[js * N_PTS + i];
        ct += g_pct[js * N_PTS + i];
    }
    float logA = __logf(fmaxf(se, 1e-30f));
    float P = (float)(ct > 0 ? ct : 1);
    g_rowloss[i] = logA - sl / P;
}

__global__ void final_kernel(float* __restrict__ out) {
    __shared__ float red[256];
    int t = threadIdx.x;
    float acc = 0.f;
#pragma unroll
    for (int it = 0; it < N_PTS / 256; it++)
        acc += g_rowloss[t + it * 256];
    red[t] = acc;
    __syncthreads();
    for (int s = 128; s > 0; s >>= 1) {
        if (t < s) red[t] += red[t + s];
        __syncthreads();
    }
    if (t == 0) out[0] = red[0];
}

extern "C" void kernel_launch(void* const* d_in, const int* in_sizes, int n_in,
                              void* d_out, int out_size) {
    const float* pts = (const float*)d_in[0];
    const long long* labs = (const long long*)d_in[1];
    prep_kernel<<<N_PTS / 256, 256>>>(pts, labs);
    dim3 grid(JSPLIT, N_PTS / BM);
    main_kernel<<<grid, NTHREADS>>>(pts);
    rowred_kernel<<<N_PTS / 256, 256>>>();
    final_kernel<<<1, 256>>>((float*)d_out);
}

// round 3
// speedup vs baseline: 1.4430x; 1.4430x over previous
#include <cuda_runtime.h>
#include <cstdint>

#define N_PTS 8192
#define DIM 64
#define BM 128
#define NT (N_PTS / BM)            // 64 tiles per side
#define NPAIR (NT * (NT + 1) / 2)  // 2080 tile pairs
#define NTHREADS 256

// Scratch (no allocation). All writes are idempotent pure functions of the
// inputs — no atomics, no zero-then-accumulate — replay/overlap safe.
__device__ float g_sq[N_PTS];
__device__ float g_ru[N_PTS];            // 1/(1-||x||^2)
__device__ int   g_lab[N_PTS];
__device__ float g_pse[NT * N_PTS];      // partial sum exp(-d), slot = other tile idx
__device__ float g_psl[NT * N_PTS];      // partial sum log r over positives
__device__ int   g_pct[NT * N_PTS];      // partial positive counts
__device__ float g_rowloss[N_PTS];

__global__ void prep_kernel(const float* __restrict__ pts,
                            const long long* __restrict__ labs) {
    int i = blockIdx.x * blockDim.x + threadIdx.x;
    if (i >= N_PTS) return;
    const float4* p = (const float4*)(pts + i * DIM);
    float s = 0.f;
#pragma unroll
    for (int q = 0; q < DIM / 4; q++) {
        float4 v = p[q];
        s += v.x * v.x + v.y * v.y + v.z * v.z + v.w * v.w;
    }
    g_sq[i] = s;
    g_ru[i] = 1.0f / (1.0f - s);
    g_lab[i] = (int)labs[i];
}

__device__ __forceinline__ float fast_sqrt(float x) {
    float r; asm("sqrt.approx.f32 %0, %1;" : "=f"(r) : "f"(x)); return r;
}
__device__ __forceinline__ float fast_rcp(float x) {
    float r; asm("rcp.approx.f32 %0, %1;" : "=f"(r) : "f"(x)); return r;
}

__global__ __launch_bounds__(NTHREADS)
void main_kernel(const float* __restrict__ pts) {
    __shared__ float As[DIM * BM];   // 32KB  [k][m], resident whole block
    __shared__ float Bs[32 * BM];    // 16KB  [kk][n], two k-halves
    const float4* P4 = (const float4*)pts;
    int tid = threadIdx.x;
    int tx = tid & 15, ty = tid >> 4;

    // Decode linear block -> upper-triangular tile pair (ti <= tj).
    int b = blockIdx.x;
    int ti = (int)floorf((129.0f - sqrtf(16641.0f - 8.0f * (float)b)) * 0.5f);
    if (ti < 0) ti = 0;
    if (ti > NT - 1) ti = NT - 1;
    while (ti > 0 && b < ti * (129 - ti) / 2) ti--;
    while (b >= (ti + 1) * (128 - ti) / 2) ti++;
    int tj = ti + (b - ti * (129 - ti) / 2);
    bool isdiag = (ti == tj);
    int i0 = ti * BM, j0 = tj * BM;

    // Load A tile transposed [k][m]
#pragma unroll
    for (int it = 0; it < (BM * DIM / 4) / NTHREADS; it++) {
        int idx = tid + it * NTHREADS;
        int m = idx & (BM - 1);
        int q = idx >> 7;
        float4 v = P4[(i0 + m) * (DIM / 4) + q];
        As[(4 * q + 0) * BM + m] = v.x;
        As[(4 * q + 1) * BM + m] = v.y;
        As[(4 * q + 2) * BM + m] = v.z;
        As[(4 * q + 3) * BM + m] = v.w;
    }

    float acc[8][8];
#pragma unroll
    for (int r = 0; r < 8; r++)
#pragma unroll
        for (int c = 0; c < 8; c++) acc[r][c] = 0.f;

#pragma unroll
    for (int kh = 0; kh < 2; kh++) {
        __syncthreads();
#pragma unroll
        for (int it = 0; it < (BM * 32 / 4) / NTHREADS; it++) {
            int idx = tid + it * NTHREADS;
            int n = idx & (BM - 1);
            int q = idx >> 7;
            float4 v = P4[(j0 + n) * (DIM / 4) + kh * 8 + q];
            Bs[(4 * q + 0) * BM + n] = v.x;
            Bs[(4 * q + 1) * BM + n] = v.y;
            Bs[(4 * q + 2) * BM + n] = v.z;
            Bs[(4 * q + 3) * BM + n] = v.w;
        }
        __syncthreads();
#pragma unroll
        for (int kk = 0; kk < 32; kk++) {
            int k = kh * 32 + kk;
            float4 a0 = *(const float4*)&As[k * BM + ty * 4];
            float4 a1 = *(const float4*)&As[k * BM + 64 + ty * 4];
            float4 b0 = *(const float4*)&Bs[kk * BM + tx * 4];
            float4 b1 = *(const float4*)&Bs[kk * BM + 64 + tx * 4];
            float a[8] = {a0.x, a0.y, a0.z, a0.w, a1.x, a1.y, a1.z, a1.w};
            float bb[8] = {b0.x, b0.y, b0.z, b0.w, b1.x, b1.y, b1.z, b1.w};
#pragma unroll
            for (int r = 0; r < 8; r++)
#pragma unroll
                for (int c = 0; c < 8; c++)
                    acc[r][c] = fmaf(a[r], bb[c], acc[r][c]);
        }
    }

    // ---- Epilogue: r = exp(-arccosh(z)) = 1/(z + sqrt(z^2-1)); log r = -d.
    int gj[8], labj[8];
    float sqj[8], ruj[8];
#pragma unroll
    for (int c = 0; c < 8; c++) {
        int col = ((c & 4) << 4) + tx * 4 + (c & 3);
        int g = j0 + col;
        gj[c] = g; sqj[c] = g_sq[g]; ruj[c] = g_ru[g]; labj[c] = g_lab[g];
    }

    float sec[8], prc[8]; int ctc[8];
#pragma unroll
    for (int c = 0; c < 8; c++) { sec[c] = 0.f; prc[c] = 1.f; ctc[c] = 0; }

#pragma unroll
    for (int r = 0; r < 8; r++) {
        int row = ((r & 4) << 4) + ty * 4 + (r & 3);
        int gi = i0 + row;
        float sqi  = g_sq[gi];
        float rui2 = 2.0f * g_ru[gi];
        int   labi = g_lab[gi];
        float ser = 0.f, prr = 1.f;
        int ctr = 0;
#pragma unroll
        for (int c = 0; c < 8; c++) {
            float sqd = fmaxf(fmaf(-2.0f, acc[r][c], sqi + sqj[c]), 0.f);
            float z = fmaf(sqd * rui2, ruj[c], 1.0f);
            z = fmaxf(z, 1.0f + 1e-7f);
            float t = fmaf(z, z, -1.0f);
            float s = fast_sqrt(t);
            float rv = fast_rcp(z + s);          // exp(-d), no cancellation
            bool offd = (gi != gj[c]);
            bool pos = offd && (labi == labj[c]);
            float rve = offd ? rv : 0.f;
            float rvp = pos ? rv : 1.f;
            ser += rve;  prr *= rvp;  ctr += pos;
            sec[c] += rve; prc[c] *= rvp; ctc[c] += pos;
        }
        // row-side reduce over tx (16 consecutive lanes share ty)
        float slr = __log2f(prr) * 0.69314718055994531f;
#pragma unroll
        for (int s = 8; s > 0; s >>= 1) {
            ser += __shfl_xor_sync(0xffffffffu, ser, s);
            slr += __shfl_xor_sync(0xffffffffu, slr, s);
            ctr += __shfl_xor_sync(0xffffffffu, ctr, s);
        }
        if (tx == 0) {
            int slot = tj * N_PTS + gi;
            g_pse[slot] = ser;
            g_psl[slot] = slr;
            g_pct[slot] = ctr;
        }
    }

    // ---- col-side (j rows) reduce over ty: shfl(16) pairs, then smem stage.
    if (!isdiag) {
        float slc[8];
#pragma unroll
        for (int c = 0; c < 8; c++) {
            slc[c] = __log2f(prc[c]) * 0.69314718055994531f;
            sec[c] += __shfl_xor_sync(0xffffffffu, sec[c], 16);
            slc[c] += __shfl_xor_sync(0xffffffffu, slc[c], 16);
            ctc[c] += __shfl_xor_sync(0xffffffffu, ctc[c], 16);
        }
        __syncthreads();                 // As dead after GEMM; reuse as scratch
        float* sse = As;                 // [8 warps][16 tx][8 c] = 1024 floats
        float* ssl = As + 1024;
        int*   sct = (int*)(As + 2048);
        int w = tid >> 5;
        if ((tid & 31) < 16) {
#pragma unroll
            for (int c = 0; c < 8; c++) {
                int o = (w * 16 + tx) * 8 + c;
                sse[o] = sec[c]; ssl[o] = slc[c]; sct[o] = ctc[c];
            }
        }
        __syncthreads();
        if (tid < 128) {
            int txq = tid >> 3, cq = tid & 7;
            float se = 0.f, sl = 0.f; int ct = 0;
#pragma unroll
            for (int ww = 0; ww < 8; ww++) {
                int o = (ww * 16 + txq) * 8 + cq;
                se += sse[o]; sl += ssl[o]; ct += sct[o];
            }
            int col = ((cq & 4) << 4) + txq * 4 + (cq & 3);
            int slot = ti * N_PTS + (j0 + col);
            g_pse[slot] = se;
            g_psl[slot] = sl;
            g_pct[slot] = ct;
        }
    }
}

// Fold the 64 tile-slot partials per row (fixed-order, deterministic).
__global__ void rowred_kernel() {
    int i = blockIdx.x * blockDim.x + threadIdx.x;
    if (i >= N_PTS) return;
    float se = 0.f, sl = 0.f;
    int ct = 0;
#pragma unroll 8
    for (int t = 0; t < NT; t++) {
        se += g_pse[t * N_PTS + i];
        sl += g_psl[t * N_PTS + i];
        ct += g_pct[t * N_PTS + i];
    }
    float logA = __logf(fmaxf(se, 1e-30f));
    float P = (float)(ct > 0 ? ct : 1);
    g_rowloss[i] = logA - sl / P;
}

__global__ void final_kernel(float* __restrict__ out) {
    __shared__ float red[256];
    int t = threadIdx.x;
    float acc = 0.f;
#pragma unroll
    for (int it = 0; it < N_PTS / 256; it++)
        acc += g_rowloss[t + it * 256];
    red[t] = acc;
    __syncthreads();
    for (int s = 128; s > 0; s >>= 1) {
        if (t < s) red[t] += red[t + s];
        __syncthreads();
    }
    if (t == 0) out[0] = red[0];
}

extern "C" void kernel_launch(void* const* d_in, const int* in_sizes, int n_in,
                              void* d_out, int out_size) {
    const float* pts = (const float*)d_in[0];
    const long long* labs = (const long long*)d_in[1];
    prep_kernel<<<N_PTS / 256, 256>>>(pts, labs);
    main_kernel<<<NPAIR, NTHREADS>>>(pts);
    rowred_kernel<<<N_PTS / 256, 256>>>();
    final_kernel<<<1, 256>>>((float*)d_out);
}